// round 15
// baseline (speedup 1.0000x reference)
#include <cuda_runtime.h>
#include <cuda_fp16.h>
#include <cuda_bf16.h>
#include <cstdint>

// Problem constants (fixed by the reference)
#define NN   50000
#define EE   1600000
#define FIN  512
#define FHID 256
#define FOUT 128
#define EPSF 1e-5f

#define NBLK_STATS 1024
#define SCAN_B 1024
#define NSCAN  ((NN + SCAN_B - 1) / SCAN_B)   // 49

// ---------------- device scratch (static, allocation-free) ----------------
__device__ __half g_h1pre[(size_t)NN * FHID];   // fp16: halves agg gather traffic
__device__ float  g_h1   [(size_t)NN * FHID];
__device__ __half g_h2pre[(size_t)NN * FOUT];
__device__ float  g_h2   [(size_t)NN * FOUT];
__device__ int   g_colsrc[EE];
__device__ float g_colw  [EE];
__device__ int   g_deg   [NN];
__device__ float g_dinv  [NN];
__device__ int   g_rowptr[NN + 1];
__device__ int   g_cursor[NN];
__device__ int   g_blocksum[64];
__device__ int   g_blockoff[64];
__device__ float g_ps [NBLK_STATS];
__device__ float g_pss[NBLK_STATS];
__device__ float g_a[FIN];   // per-k LN affine scale (max K = 512)
__device__ float g_c[FIN];   // per-k LN affine shift
__device__ float g_colsum[FOUT];
__device__ float g_ss2;
__device__ float g_ssum;     // fused LN1 stats (written by agg1)
__device__ float g_sss;

// ---------------- helpers ----------------
__device__ __forceinline__ uint32_t smem_u32(const void* p) {
    uint32_t a;
    asm("{ .reg .u64 t; cvta.to.shared.u64 t, %1; cvt.u32.u64 %0, t; }" : "=r"(a) : "l"(p));
    return a;
}

__device__ __forceinline__ void mma_fp16(float c[4], const uint32_t a[4], const uint32_t b[2]) {
    asm volatile(
        "mma.sync.aligned.m16n8k16.row.col.f32.f16.f16.f32 "
        "{%0,%1,%2,%3}, {%4,%5,%6,%7}, {%8,%9}, {%0,%1,%2,%3};"
        : "+f"(c[0]), "+f"(c[1]), "+f"(c[2]), "+f"(c[3])
        : "r"(a[0]), "r"(a[1]), "r"(a[2]), "r"(a[3]), "r"(b[0]), "r"(b[1]));
}

__device__ __forceinline__ void ldsm_x4(uint32_t r[4], uint32_t a) {
    asm volatile("ldmatrix.sync.aligned.m8n8.x4.shared.b16 {%0,%1,%2,%3}, [%4];"
                 : "=r"(r[0]), "=r"(r[1]), "=r"(r[2]), "=r"(r[3]) : "r"(a));
}
__device__ __forceinline__ void ldsm_x4_t(uint32_t r[4], uint32_t a) {
    asm volatile("ldmatrix.sync.aligned.m8n8.x4.trans.shared.b16 {%0,%1,%2,%3}, [%4];"
                 : "=r"(r[0]), "=r"(r[1]), "=r"(r[2]), "=r"(r[3]) : "r"(a));
}

__device__ __forceinline__ float4 h4_to_f4(uint2 u) {
    float2 f0 = __half22float2(*(__half2*)&u.x);
    float2 f1 = __half22float2(*(__half2*)&u.y);
    return make_float4(f0.x, f0.y, f1.x, f1.y);
}

// ---------------- init: reset accumulators every replay ----------------
__global__ void k_init() {
    int i = blockIdx.x * blockDim.x + threadIdx.x;
    if (i < NN) g_deg[i] = 1;                 // self-loop
    if (i < FOUT) g_colsum[i] = 0.f;
    if (i == FOUT) { g_ss2 = 0.f; g_ssum = 0.f; g_sss = 0.f; }
}

// ---------------- sum / sumsq partials over x (vectorized grid-stride) ----------------
__global__ void k_stats(const float* __restrict__ p, int n4) {
    float s = 0.f, ss = 0.f;
    int stride = gridDim.x * blockDim.x;
    for (int i = blockIdx.x * blockDim.x + threadIdx.x; i < n4; i += stride) {
        float4 v = ((const float4*)p)[i];
        s  += v.x + v.y + v.z + v.w;
        ss += v.x * v.x + v.y * v.y + v.z * v.z + v.w * v.w;
    }
    __shared__ float sh[256], sh2[256];
    sh[threadIdx.x] = s; sh2[threadIdx.x] = ss;
    __syncthreads();
    for (int o = 128; o > 0; o >>= 1) {
        if (threadIdx.x < o) { sh[threadIdx.x] += sh[threadIdx.x + o]; sh2[threadIdx.x] += sh2[threadIdx.x + o]; }
        __syncthreads();
    }
    if (threadIdx.x == 0) { g_ps[blockIdx.x] = sh[0]; g_pss[blockIdx.x] = sh2[0]; }
}

// ---------------- finalize LN0 stats -> per-k affine a,c ----------------
__global__ void k_finalize_ln(float invM, const float* __restrict__ w,
                              const float* __restrict__ b, int K) {
    __shared__ float sh[256], sh2[256];
    int tid = threadIdx.x;
    float s = 0.f, ss = 0.f;
    for (int i = tid; i < NBLK_STATS; i += 256) { s += g_ps[i]; ss += g_pss[i]; }
    sh[tid] = s; sh2[tid] = ss;
    __syncthreads();
    for (int o = 128; o > 0; o >>= 1) {
        if (tid < o) { sh[tid] += sh[tid + o]; sh2[tid] += sh2[tid + o]; }
        __syncthreads();
    }
    __shared__ float smean, srs;
    if (tid == 0) {
        float mean = sh[0] * invM;
        float var  = sh2[0] * invM - mean * mean;
        smean = mean;
        srs = rsqrtf(var + EPSF);
    }
    __syncthreads();
    for (int k = tid; k < K; k += 256) {
        float wk = w[k];
        g_a[k] = srs * wk;
        g_c[k] = fmaf(-srs * smean, wk, b[k]);
    }
}

// ---------------- finalize LN1 stats (fused agg scalars) ----------------
__global__ void k_finalize_ln_s(float invM, const float* __restrict__ w,
                                const float* __restrict__ b, int K) {
    float mean = g_ssum * invM;
    float var  = g_sss * invM - mean * mean;
    float rs   = rsqrtf(var + EPSF);
    for (int k = threadIdx.x; k < K; k += blockDim.x) {
        float wk = w[k];
        g_a[k] = rs * wk;
        g_c[k] = fmaf(-rs * mean, wk, b[k]);
    }
}

// ---------------- degree histogram ----------------
__global__ void k_deg(const int* __restrict__ dst) {
    int e = blockIdx.x * blockDim.x + threadIdx.x;
    if (e < EE) atomicAdd(&g_deg[dst[e]], 1);
}

// ---------------- exclusive scan over in-degree counts -> row_ptr ----------------
__global__ void k_scan1() {
    __shared__ int s[SCAN_B];
    int tid = threadIdx.x;
    int n = blockIdx.x * SCAN_B + tid;
    int cnt = (n < NN) ? (g_deg[n] - 1) : 0;   // exclude self-loop
    s[tid] = cnt;
    __syncthreads();
    for (int off = 1; off < SCAN_B; off <<= 1) {
        int v = (tid >= off) ? s[tid - off] : 0;
        __syncthreads();
        s[tid] += v;
        __syncthreads();
    }
    if (n < NN) g_rowptr[n] = s[tid] - cnt;     // exclusive
    if (tid == SCAN_B - 1) g_blocksum[blockIdx.x] = s[SCAN_B - 1];
}
__global__ void k_scan2(int nb) {
    if (threadIdx.x == 0) {
        int acc = 0;
        for (int b = 0; b < nb; b++) { g_blockoff[b] = acc; acc += g_blocksum[b]; }
    }
}
__global__ void k_scan3() {
    int n = blockIdx.x * blockDim.x + threadIdx.x;
    if (n < NN) {
        int r = g_rowptr[n] + g_blockoff[n >> 10];
        g_rowptr[n] = r;
        g_cursor[n] = r;
        g_dinv[n] = rsqrtf((float)g_deg[n]);
    }
    if (n == 0) g_rowptr[NN] = EE;
}

// ---------------- CSR scatter ----------------
__global__ void k_scatter(const int* __restrict__ src, const int* __restrict__ dst) {
    int e = blockIdx.x * blockDim.x + threadIdx.x;
    if (e < EE) {
        int d = dst[e], s = src[e];
        int pos = atomicAdd(&g_cursor[d], 1);
        g_colsrc[pos] = s;
        g_colw[pos]   = g_dinv[s] * g_dinv[d];
    }
}

// ---------------- fp16 tensor-core GEMM: LN affine fused, ldmatrix, full-N tile ----
// Y(fp16) = (a.*X + c) @ W. Single m16n8k16 fp16 MMA per k-step (f32 accum).
// BM=128, BN=N_ (full width: A loaded/affined ONCE), BK=16.
// 256 threads = 8 warps (2x4), warp tile 64 x (N_/4).
// Single-buffered (measured faster than double in R14); affine via LDS.128.
template <int K_, int N_, bool X_FROM_H1>
__global__ __launch_bounds__(256) void k_gemm_fp16(const float* __restrict__ Xin,
                                                   const float* __restrict__ W) {
    constexpr int BM = 128, BK = 16;
    constexpr int NB = N_ / 128;          // float4 column groups per thread (B path)
    constexpr int NT = N_ / 32;           // 8-col mma tiles per warp
    constexpr int ASTR = 48;              // bytes per A row
    constexpr int BSTR = 2 * N_ + 16;     // bytes per B row (row advance = 4 banks)
    __shared__ __align__(16) uint8_t Asm[BM * ASTR];
    __shared__ __align__(16) uint8_t Bsm[BK * BSTR];
    __shared__ __align__(16) float sA[K_];
    __shared__ __align__(16) float sC[K_];

    const float* __restrict__ X = X_FROM_H1 ? (const float*)g_h1 : Xin;
    __half* __restrict__ Y = X_FROM_H1 ? (__half*)g_h2pre : (__half*)g_h1pre;

    int tid = threadIdx.x;
    for (int i = tid; i < K_; i += 256) { sA[i] = g_a[i]; sC[i] = g_c[i]; }
    __syncthreads();

    int by = blockIdx.y;
    int warp = tid >> 5, lane = tid & 31;
    int wr = warp >> 2, wc = warp & 3;     // 2 x 4 warp grid
    int g  = lane >> 2, tc = lane & 3;
    int l15 = lane & 15, lhi = lane >> 4;

    // ---- global load geometry (fixed per thread) ----
    int ar[2], acg[2]; bool aok[2];
    const float* aptr[2];
#pragma unroll
    for (int h = 0; h < 2; h++) {
        int i = tid + h * 256;          // 0..511 float4 index
        ar[h]  = i >> 2;                // row in tile 0..127
        acg[h] = (i & 3) * 4;           // k offset 0,4,8,12
        int row = by * BM + ar[h];
        aok[h] = row < NN;
        aptr[h] = X + (size_t)(aok[h] ? row : 0) * K_ + acg[h];
    }
    int bk2 = tid >> 5;                 // k-pair 0..7 (rows 2*bk2, 2*bk2+1)
    int bc4 = lane * 4;                 // base col 0..124 (plus j*128)
    const float* bptr = W + (size_t)(2 * bk2) * N_ + bc4;

    // ---- ldmatrix fragment addresses (fixed per thread) ----
    uint32_t Ab = smem_u32(Asm), Bb = smem_u32(Bsm);
    uint32_t a_addr[4], b_addr[NT / 2];
#pragma unroll
    for (int mt = 0; mt < 4; mt++)
        a_addr[mt] = Ab + (uint32_t)((wr * 64 + mt * 16 + l15) * ASTR + lhi * 16);
#pragma unroll
    for (int p = 0; p < NT / 2; p++) {
        int nb = wc * (N_ / 4) + p * 16;
        b_addr[p] = Bb + (uint32_t)(l15 * BSTR + (nb + lhi * 8) * 2);
    }

    // ---- prefetch chunk 0 ----
    float4 pa[2], pb0[NB], pb1[NB];
#pragma unroll
    for (int h = 0; h < 2; h++)
        pa[h] = aok[h] ? *(const float4*)aptr[h] : make_float4(0.f, 0.f, 0.f, 0.f);
#pragma unroll
    for (int j = 0; j < NB; j++) {
        pb0[j] = *(const float4*)(bptr + j * 128);
        pb1[j] = *(const float4*)(bptr + N_ + j * 128);
    }

    float acc[4][NT][4];
#pragma unroll
    for (int i = 0; i < 4; i++)
#pragma unroll
        for (int j = 0; j < NT; j++)
#pragma unroll
            for (int q = 0; q < 4; q++) acc[i][j][q] = 0.f;

    for (int k0 = 0; k0 < K_; k0 += BK) {
        // ---- store prefetched A (LN affine via vector LDS + fp16, row-major [m][k]) ----
#pragma unroll
        for (int h = 0; h < 2; h++) {
            int r = ar[h], cg = acg[h];
            float4 av = *(const float4*)&sA[k0 + cg];   // LDS.128 (16B aligned)
            float4 cv = *(const float4*)&sC[k0 + cg];
            float f0 = fmaf(av.x, pa[h].x, cv.x);
            float f1 = fmaf(av.y, pa[h].y, cv.y);
            float f2 = fmaf(av.z, pa[h].z, cv.z);
            float f3 = fmaf(av.w, pa[h].w, cv.w);
            __half2 u0 = __floats2half2_rn(f0, f1);
            __half2 u1 = __floats2half2_rn(f2, f3);
            uint2 u = make_uint2(*(uint32_t*)&u0, *(uint32_t*)&u1);
            *(uint2*)(Asm + r * ASTR + cg * 2) = u;
        }
        // ---- store prefetched B (pack fp16, row-major [k][n]) ----
#pragma unroll
        for (int j = 0; j < NB; j++) {
            __half2 p00 = __floats2half2_rn(pb0[j].x, pb0[j].y);
            __half2 p01 = __floats2half2_rn(pb0[j].z, pb0[j].w);
            __half2 p10 = __floats2half2_rn(pb1[j].x, pb1[j].y);
            __half2 p11 = __floats2half2_rn(pb1[j].z, pb1[j].w);
            uint2 r0 = make_uint2(*(uint32_t*)&p00, *(uint32_t*)&p01);
            uint2 r1 = make_uint2(*(uint32_t*)&p10, *(uint32_t*)&p11);
            int colb = (bc4 + j * 128) * 2;
            *(uint2*)(Bsm + (2 * bk2    ) * BSTR + colb) = r0;
            *(uint2*)(Bsm + (2 * bk2 + 1) * BSTR + colb) = r1;
        }
        __syncthreads();

        // ---- issue next chunk's global loads (overlap with MMAs below) ----
        if (k0 + BK < K_) {
#pragma unroll
            for (int h = 0; h < 2; h++)
                pa[h] = aok[h] ? *(const float4*)(aptr[h] + k0 + BK)
                               : make_float4(0.f, 0.f, 0.f, 0.f);
            const float* bp = bptr + (size_t)(k0 + BK) * N_;
#pragma unroll
            for (int j = 0; j < NB; j++) {
                pb0[j] = *(const float4*)(bp + j * 128);
                pb1[j] = *(const float4*)(bp + N_ + j * 128);
            }
        }

        // ---- fragments via ldmatrix + 4*NT MMAs ----
        uint32_t ah[4][4], bh[NT][2];
#pragma unroll
        for (int mt = 0; mt < 4; mt++)
            ldsm_x4(ah[mt], a_addr[mt]);
#pragma unroll
        for (int p = 0; p < NT / 2; p++) {
            uint32_t t[4];
            ldsm_x4_t(t, b_addr[p]);
            bh[2 * p    ][0] = t[0]; bh[2 * p    ][1] = t[1];
            bh[2 * p + 1][0] = t[2]; bh[2 * p + 1][1] = t[3];
        }
#pragma unroll
        for (int mt = 0; mt < 4; mt++)
#pragma unroll
            for (int nt = 0; nt < NT; nt++)
                mma_fp16(acc[mt][nt], ah[mt], bh[nt]);
        __syncthreads();
    }

    // ---- epilogue: fp16 stores ----
#pragma unroll
    for (int mt = 0; mt < 4; mt++) {
        int r0 = by * BM + wr * 64 + mt * 16 + g;
        int r1 = r0 + 8;
#pragma unroll
        for (int nt = 0; nt < NT; nt++) {
            int col = wc * (N_ / 4) + nt * 8 + 2 * tc;
            if (r0 < NN)
                *(__half2*)(Y + (size_t)r0 * N_ + col) = __floats2half2_rn(acc[mt][nt][0], acc[mt][nt][1]);
            if (r1 < NN)
                *(__half2*)(Y + (size_t)r1 * N_ + col) = __floats2half2_rn(acc[mt][nt][2], acc[mt][nt][3]);
        }
    }
}

// ---------------- aggregation: fp16 gathers; optional fused LN stats ----------------
// blockDim = (F/4, NPB). One node per threadIdx.y. No output atomics.
template <int F, int NPB, bool SECOND, bool FUSE_STATS>
__global__ void k_agg(const float* __restrict__ bias) {
    constexpr int F4 = F / 4;
    const uint2* __restrict__ hpre = SECOND ? (const uint2*)g_h2pre : (const uint2*)g_h1pre;
    float4* __restrict__ hout      = SECOND ? (float4*)g_h2 : (float4*)g_h1;

    int n = blockIdx.x * NPB + threadIdx.y;   // NN divisible by NPB: always in range
    int f = threadIdx.x;

    float di = g_dinv[n];
    float4 self = h4_to_f4(hpre[(size_t)n * F4 + f]);
    float w_self = di * di;
    float4 acc;
    acc.x = w_self * self.x; acc.y = w_self * self.y;
    acc.z = w_self * self.z; acc.w = w_self * self.w;

    int e = g_rowptr[n];
    int end = g_rowptr[n + 1];
    for (; e + 4 <= end; e += 4) {
        int s0 = g_colsrc[e + 0], s1 = g_colsrc[e + 1];
        int s2 = g_colsrc[e + 2], s3 = g_colsrc[e + 3];
        float w0 = g_colw[e + 0], w1 = g_colw[e + 1];
        float w2 = g_colw[e + 2], w3 = g_colw[e + 3];
        float4 v0 = h4_to_f4(hpre[(size_t)s0 * F4 + f]);
        float4 v1 = h4_to_f4(hpre[(size_t)s1 * F4 + f]);
        float4 v2 = h4_to_f4(hpre[(size_t)s2 * F4 + f]);
        float4 v3 = h4_to_f4(hpre[(size_t)s3 * F4 + f]);
        acc.x = fmaf(w0, v0.x, acc.x); acc.y = fmaf(w0, v0.y, acc.y);
        acc.z = fmaf(w0, v0.z, acc.z); acc.w = fmaf(w0, v0.w, acc.w);
        acc.x = fmaf(w1, v1.x, acc.x); acc.y = fmaf(w1, v1.y, acc.y);
        acc.z = fmaf(w1, v1.z, acc.z); acc.w = fmaf(w1, v1.w, acc.w);
        acc.x = fmaf(w2, v2.x, acc.x); acc.y = fmaf(w2, v2.y, acc.y);
        acc.z = fmaf(w2, v2.z, acc.z); acc.w = fmaf(w2, v2.w, acc.w);
        acc.x = fmaf(w3, v3.x, acc.x); acc.y = fmaf(w3, v3.y, acc.y);
        acc.z = fmaf(w3, v3.z, acc.z); acc.w = fmaf(w3, v3.w, acc.w);
    }
    for (; e < end; ++e) {
        float w = g_colw[e];
        float4 v = h4_to_f4(hpre[(size_t)g_colsrc[e] * F4 + f]);
        acc.x = fmaf(w, v.x, acc.x); acc.y = fmaf(w, v.y, acc.y);
        acc.z = fmaf(w, v.z, acc.z); acc.w = fmaf(w, v.w, acc.w);
    }

    float4 b = ((const float4*)bias)[f];
    float4 o;
    o.x = fmaxf(acc.x + b.x, 0.f);
    o.y = fmaxf(acc.y + b.y, 0.f);
    o.z = fmaxf(acc.z + b.z, 0.f);
    o.w = fmaxf(acc.w + b.w, 0.f);
    hout[(size_t)n * F4 + f] = o;

    if (FUSE_STATS) {
        // block-reduce sum & sumsq of outputs -> scalar atomics (LN1 stats)
        constexpr int NT2 = F4 * NPB;
        __shared__ float rs[NT2], rq[NT2];
        int t = threadIdx.y * F4 + threadIdx.x;
        rs[t] = o.x + o.y + o.z + o.w;
        rq[t] = o.x * o.x + o.y * o.y + o.z * o.z + o.w * o.w;
        __syncthreads();
        for (int off = NT2 / 2; off > 0; off >>= 1) {
            if (t < off) { rs[t] += rs[t + off]; rq[t] += rq[t + off]; }
            __syncthreads();
        }
        if (t == 0) { atomicAdd(&g_ssum, rs[0]); atomicAdd(&g_sss, rq[0]); }
    }
}

// ---------------- reduce h2: column sums + global sumsq (512 blocks: atomics OK) ----
__global__ void k_reduce_h2() {
    int tid = threadIdx.x;
    float col = 0.f, ss = 0.f;
    int stride = gridDim.x * 256;     // multiple of 128 -> fixed channel per thread
    for (int i = blockIdx.x * 256 + tid; i < NN * FOUT; i += stride) {
        float v = g_h2[i];
        col += v;
        ss += v * v;
    }
    __shared__ float shc[256], shs[256];
    shc[tid] = col; shs[tid] = ss;
    __syncthreads();
    if (tid < 128) shc[tid] += shc[tid + 128];  // same channel pairing
    for (int o = 128; o > 0; o >>= 1) {
        if (tid < o) shs[tid] += shs[tid + o];
        __syncthreads();
    }
    if (tid < 128) atomicAdd(&g_colsum[tid], shc[tid]);
    if (tid == 0)  atomicAdd(&g_ss2, shs[0]);
}

// ---------------- final LN2 + global mean pool -> out[1,128] ----------------
__global__ void k_final(const float* __restrict__ w, const float* __restrict__ b,
                        float* __restrict__ out) {
    __shared__ float sh[128];
    int tid = threadIdx.x;
    float cs = g_colsum[tid];
    sh[tid] = cs;
    __syncthreads();
    for (int o = 64; o > 0; o >>= 1) {
        if (tid < o) sh[tid] += sh[tid + o];
        __syncthreads();
    }
    float invM = 1.f / (float)((size_t)NN * FOUT);
    float mean = sh[0] * invM;
    float var  = g_ss2 * invM - mean * mean;
    float rs   = rsqrtf(var + EPSF);
    out[tid] = (cs * (1.f / (float)NN) - mean) * rs * w[tid] + b[tid];
}

// ---------------- launch ----------------
extern "C" void kernel_launch(void* const* d_in, const int* in_sizes, int n_in,
                              void* d_out, int out_size) {
    const float* x    = (const float*)d_in[0];
    const int*   ei   = (const int*)d_in[1];
    const float* W1   = (const float*)d_in[2];
    const float* b1   = (const float*)d_in[3];
    const float* W2   = (const float*)d_in[4];
    const float* b2   = (const float*)d_in[5];
    const float* ln0w = (const float*)d_in[6];
    const float* ln0b = (const float*)d_in[7];
    const float* ln1w = (const float*)d_in[8];
    const float* ln1b = (const float*)d_in[9];
    const float* ln2w = (const float*)d_in[10];
    const float* ln2b = (const float*)d_in[11];
    const int* src = ei;
    const int* dst = ei + EE;
    float* out = (float*)d_out;

    dim3 nb256((NN + 255) / 256, 1, 1);
    dim3 eb256((EE + 255) / 256, 1, 1);

    // launches 1-3: LN0 stats/finalize + init (GEMM1 must be 4th -> profiled)
    k_stats<<<NBLK_STATS, 256>>>(x, (NN * FIN) / 4);
    k_finalize_ln<<<1, 256>>>(1.f / (float)((size_t)NN * FIN), ln0w, ln0b, FIN);
    k_init<<<nb256, 256>>>();

    // 4: layer-1 GEMM (profiled launch) — full-N block tile, A loaded once
    k_gemm_fp16<FIN, FHID, false><<<dim3(1, (NN + 127) / 128), 256>>>(x, W1);

    // CSR build
    k_deg<<<eb256, 256>>>(dst);
    k_scan1<<<NSCAN, SCAN_B>>>();
    k_scan2<<<1, 32>>>(NSCAN);
    k_scan3<<<nb256, 256>>>();
    k_scatter<<<eb256, 256>>>(src, dst);

    // layer 1 aggregate + bias + relu (+ fused LN1 stats)
    k_agg<FHID, 2, false, true><<<NN / 2, dim3(64, 2)>>>(b1);
    k_finalize_ln_s<<<1, 256>>>(1.f / (float)((size_t)NN * FHID), ln1w, ln1b, FHID);

    // layer 2 GEMM + aggregate
    k_gemm_fp16<FHID, FOUT, true><<<dim3(1, (NN + 127) / 128), 256>>>(nullptr, W2);
    k_agg<FOUT, 4, true, false><<<NN / 4, dim3(32, 4)>>>(b2);

    // ln2 + mean pool (512-block partial reduce keeps per-address atomic rate low)
    k_reduce_h2<<<512, 256>>>();
    k_final<<<1, FOUT>>>(ln2w, ln2b, out);
}

// round 16
// speedup vs baseline: 1.0332x; 1.0332x over previous
#include <cuda_runtime.h>
#include <cuda_fp16.h>
#include <cuda_bf16.h>
#include <cstdint>

// Problem constants (fixed by the reference)
#define NN   50000
#define EE   1600000
#define FIN  512
#define FHID 256
#define FOUT 128
#define EPSF 1e-5f

#define NBLK_STATS 1024
#define SCAN_B 1024
#define NSCAN  ((NN + SCAN_B - 1) / SCAN_B)   // 49

// ---------------- device scratch (static, allocation-free) ----------------
__device__ __half g_h1pre[(size_t)NN * FHID];   // fp16: halves agg gather traffic
__device__ float  g_h1   [(size_t)NN * FHID];
__device__ __half g_h2pre[(size_t)NN * FOUT];
__device__ float  g_h2   [(size_t)NN * FOUT];
__device__ int   g_colsrc[EE];
__device__ float g_colw  [EE];
__device__ int   g_deg   [NN];
__device__ float g_dinv  [NN];
__device__ int   g_rowptr[NN + 1];
__device__ int   g_cursor[NN];
__device__ int   g_blocksum[64];
__device__ int   g_blockoff[64];
__device__ float g_ps [NBLK_STATS];
__device__ float g_pss[NBLK_STATS];
__device__ float g_a[FIN];   // per-k LN affine scale (max K = 512)
__device__ float g_c[FIN];   // per-k LN affine shift
__device__ float g_colsum[FOUT];
__device__ float g_ss2;
__device__ float g_ssum;     // fused LN1 stats (written by agg1)
__device__ float g_sss;

// ---------------- helpers ----------------
__device__ __forceinline__ uint32_t smem_u32(const void* p) {
    uint32_t a;
    asm("{ .reg .u64 t; cvta.to.shared.u64 t, %1; cvt.u32.u64 %0, t; }" : "=r"(a) : "l"(p));
    return a;
}

__device__ __forceinline__ void mma_fp16(float c[4], const uint32_t a[4], const uint32_t b[2]) {
    asm volatile(
        "mma.sync.aligned.m16n8k16.row.col.f32.f16.f16.f32 "
        "{%0,%1,%2,%3}, {%4,%5,%6,%7}, {%8,%9}, {%0,%1,%2,%3};"
        : "+f"(c[0]), "+f"(c[1]), "+f"(c[2]), "+f"(c[3])
        : "r"(a[0]), "r"(a[1]), "r"(a[2]), "r"(a[3]), "r"(b[0]), "r"(b[1]));
}

__device__ __forceinline__ void ldsm_x4(uint32_t r[4], uint32_t a) {
    asm volatile("ldmatrix.sync.aligned.m8n8.x4.shared.b16 {%0,%1,%2,%3}, [%4];"
                 : "=r"(r[0]), "=r"(r[1]), "=r"(r[2]), "=r"(r[3]) : "r"(a));
}
__device__ __forceinline__ void ldsm_x4_t(uint32_t r[4], uint32_t a) {
    asm volatile("ldmatrix.sync.aligned.m8n8.x4.trans.shared.b16 {%0,%1,%2,%3}, [%4];"
                 : "=r"(r[0]), "=r"(r[1]), "=r"(r[2]), "=r"(r[3]) : "r"(a));
}

__device__ __forceinline__ float4 h4_to_f4(uint2 u) {
    float2 f0 = __half22float2(*(__half2*)&u.x);
    float2 f1 = __half22float2(*(__half2*)&u.y);
    return make_float4(f0.x, f0.y, f1.x, f1.y);
}

// ---------------- init: reset accumulators every replay ----------------
__global__ void k_init() {
    int i = blockIdx.x * blockDim.x + threadIdx.x;
    if (i < NN) g_deg[i] = 1;                 // self-loop
    if (i < FOUT) g_colsum[i] = 0.f;
    if (i == FOUT) { g_ss2 = 0.f; g_ssum = 0.f; g_sss = 0.f; }
}

// ---------------- sum / sumsq partials over x (vectorized grid-stride) ----------------
__global__ void k_stats(const float* __restrict__ p, int n4) {
    float s = 0.f, ss = 0.f;
    int stride = gridDim.x * blockDim.x;
    for (int i = blockIdx.x * blockDim.x + threadIdx.x; i < n4; i += stride) {
        float4 v = ((const float4*)p)[i];
        s  += v.x + v.y + v.z + v.w;
        ss += v.x * v.x + v.y * v.y + v.z * v.z + v.w * v.w;
    }
    __shared__ float sh[256], sh2[256];
    sh[threadIdx.x] = s; sh2[threadIdx.x] = ss;
    __syncthreads();
    for (int o = 128; o > 0; o >>= 1) {
        if (threadIdx.x < o) { sh[threadIdx.x] += sh[threadIdx.x + o]; sh2[threadIdx.x] += sh2[threadIdx.x + o]; }
        __syncthreads();
    }
    if (threadIdx.x == 0) { g_ps[blockIdx.x] = sh[0]; g_pss[blockIdx.x] = sh2[0]; }
}

// ---------------- finalize LN0 stats -> per-k affine a,c ----------------
__global__ void k_finalize_ln(float invM, const float* __restrict__ w,
                              const float* __restrict__ b, int K) {
    __shared__ float sh[256], sh2[256];
    int tid = threadIdx.x;
    float s = 0.f, ss = 0.f;
    for (int i = tid; i < NBLK_STATS; i += 256) { s += g_ps[i]; ss += g_pss[i]; }
    sh[tid] = s; sh2[tid] = ss;
    __syncthreads();
    for (int o = 128; o > 0; o >>= 1) {
        if (tid < o) { sh[tid] += sh[tid + o]; sh2[tid] += sh2[tid + o]; }
        __syncthreads();
    }
    __shared__ float smean, srs;
    if (tid == 0) {
        float mean = sh[0] * invM;
        float var  = sh2[0] * invM - mean * mean;
        smean = mean;
        srs = rsqrtf(var + EPSF);
    }
    __syncthreads();
    for (int k = tid; k < K; k += 256) {
        float wk = w[k];
        g_a[k] = srs * wk;
        g_c[k] = fmaf(-srs * smean, wk, b[k]);
    }
}

// ---------------- finalize LN1 stats (fused agg scalars) ----------------
__global__ void k_finalize_ln_s(float invM, const float* __restrict__ w,
                                const float* __restrict__ b, int K) {
    float mean = g_ssum * invM;
    float var  = g_sss * invM - mean * mean;
    float rs   = rsqrtf(var + EPSF);
    for (int k = threadIdx.x; k < K; k += blockDim.x) {
        float wk = w[k];
        g_a[k] = rs * wk;
        g_c[k] = fmaf(-rs * mean, wk, b[k]);
    }
}

// ---------------- degree histogram ----------------
__global__ void k_deg(const int* __restrict__ dst) {
    int e = blockIdx.x * blockDim.x + threadIdx.x;
    if (e < EE) atomicAdd(&g_deg[dst[e]], 1);
}

// ---------------- exclusive scan over in-degree counts -> row_ptr ----------------
__global__ void k_scan1() {
    __shared__ int s[SCAN_B];
    int tid = threadIdx.x;
    int n = blockIdx.x * SCAN_B + tid;
    int cnt = (n < NN) ? (g_deg[n] - 1) : 0;   // exclude self-loop
    s[tid] = cnt;
    __syncthreads();
    for (int off = 1; off < SCAN_B; off <<= 1) {
        int v = (tid >= off) ? s[tid - off] : 0;
        __syncthreads();
        s[tid] += v;
        __syncthreads();
    }
    if (n < NN) g_rowptr[n] = s[tid] - cnt;     // exclusive
    if (tid == SCAN_B - 1) g_blocksum[blockIdx.x] = s[SCAN_B - 1];
}
__global__ void k_scan2(int nb) {
    if (threadIdx.x == 0) {
        int acc = 0;
        for (int b = 0; b < nb; b++) { g_blockoff[b] = acc; acc += g_blocksum[b]; }
    }
}
__global__ void k_scan3() {
    int n = blockIdx.x * blockDim.x + threadIdx.x;
    if (n < NN) {
        int r = g_rowptr[n] + g_blockoff[n >> 10];
        g_rowptr[n] = r;
        g_cursor[n] = r;
        g_dinv[n] = rsqrtf((float)g_deg[n]);
    }
    if (n == 0) g_rowptr[NN] = EE;
}

// ---------------- CSR scatter ----------------
__global__ void k_scatter(const int* __restrict__ src, const int* __restrict__ dst) {
    int e = blockIdx.x * blockDim.x + threadIdx.x;
    if (e < EE) {
        int d = dst[e], s = src[e];
        int pos = atomicAdd(&g_cursor[d], 1);
        g_colsrc[pos] = s;
        g_colw[pos]   = g_dinv[s] * g_dinv[d];
    }
}

// ---------------- fp16 tensor-core GEMM (round-13 measured optimum) ----------------
// Y(fp16) = (a.*X + c) @ W. Single m16n8k16 fp16 MMA per k-step (f32 accum).
// BM=128, BN=128, BK=16. 256 threads = 8 warps (2x4), warp tile 64x32.
// Single-buffered SMEM; LN affine via vector LDS.128; ldmatrix fragments.
template <int K_, int N_, bool X_FROM_H1>
__global__ __launch_bounds__(256) void k_gemm_fp16(const float* __restrict__ Xin,
                                                   const float* __restrict__ W) {
    constexpr int BM = 128, BN = 128, BK = 16;
    constexpr int ASTR = 48;    // bytes per A row
    constexpr int BSTR = 272;   // bytes per B row
    __shared__ __align__(16) uint8_t Asm[BM * ASTR];
    __shared__ __align__(16) uint8_t Bsm[BK * BSTR];
    __shared__ __align__(16) float sA[K_];
    __shared__ __align__(16) float sC[K_];

    const float* __restrict__ X = X_FROM_H1 ? (const float*)g_h1 : Xin;
    __half* __restrict__ Y = X_FROM_H1 ? (__half*)g_h2pre : (__half*)g_h1pre;

    int tid = threadIdx.x;
    for (int i = tid; i < K_; i += 256) { sA[i] = g_a[i]; sC[i] = g_c[i]; }
    __syncthreads();

    int bx = blockIdx.x, by = blockIdx.y;
    int warp = tid >> 5, lane = tid & 31;
    int wr = warp >> 2, wc = warp & 3;     // 2 x 4 warp grid
    int g  = lane >> 2, tc = lane & 3;
    int l15 = lane & 15, lhi = lane >> 4;

    // ---- global load geometry (fixed per thread) ----
    int ar[2], acg[2]; bool aok[2];
    const float* aptr[2];
#pragma unroll
    for (int h = 0; h < 2; h++) {
        int i = tid + h * 256;          // 0..511 float4 index
        ar[h]  = i >> 2;                // row in tile 0..127
        acg[h] = (i & 3) * 4;           // k offset 0,4,8,12
        int row = by * BM + ar[h];
        aok[h] = row < NN;
        aptr[h] = X + (size_t)(aok[h] ? row : 0) * K_ + acg[h];
    }
    int bk2 = tid >> 5;                 // k-pair 0..7 (rows 2*bk2, 2*bk2+1)
    int bc4 = lane * 4;                 // col 0..124
    const float* bptr = W + (size_t)(2 * bk2) * N_ + bx * BN + bc4;

    // ---- ldmatrix fragment addresses (fixed per thread) ----
    uint32_t Ab = smem_u32(Asm), Bb = smem_u32(Bsm);
    uint32_t a_addr[4], b_addr[2];
#pragma unroll
    for (int mt = 0; mt < 4; mt++)
        a_addr[mt] = Ab + (uint32_t)((wr * 64 + mt * 16 + l15) * ASTR + lhi * 16);
#pragma unroll
    for (int p = 0; p < 2; p++) {
        int nb = wc * 32 + p * 16;
        b_addr[p] = Bb + (uint32_t)(l15 * BSTR + (nb + lhi * 8) * 2);
    }

    // ---- prefetch chunk 0 ----
    float4 pa[2], pb0, pb1;
#pragma unroll
    for (int h = 0; h < 2; h++)
        pa[h] = aok[h] ? *(const float4*)aptr[h] : make_float4(0.f, 0.f, 0.f, 0.f);
    pb0 = *(const float4*)bptr;
    pb1 = *(const float4*)(bptr + N_);

    float acc[4][4][4];
#pragma unroll
    for (int i = 0; i < 4; i++)
#pragma unroll
        for (int j = 0; j < 4; j++)
#pragma unroll
            for (int q = 0; q < 4; q++) acc[i][j][q] = 0.f;

    for (int k0 = 0; k0 < K_; k0 += BK) {
        // ---- store prefetched A (LN affine via vector LDS + fp16, row-major [m][k]) ----
#pragma unroll
        for (int h = 0; h < 2; h++) {
            int r = ar[h], cg = acg[h];
            float4 av = *(const float4*)&sA[k0 + cg];   // LDS.128 (16B aligned)
            float4 cv = *(const float4*)&sC[k0 + cg];
            float f0 = fmaf(av.x, pa[h].x, cv.x);
            float f1 = fmaf(av.y, pa[h].y, cv.y);
            float f2 = fmaf(av.z, pa[h].z, cv.z);
            float f3 = fmaf(av.w, pa[h].w, cv.w);
            __half2 u0 = __floats2half2_rn(f0, f1);
            __half2 u1 = __floats2half2_rn(f2, f3);
            uint2 u = make_uint2(*(uint32_t*)&u0, *(uint32_t*)&u1);
            *(uint2*)(Asm + r * ASTR + cg * 2) = u;
        }
        // ---- store prefetched B (pack fp16, row-major [k][n]) ----
        {
            __half2 p00 = __floats2half2_rn(pb0.x, pb0.y);
            __half2 p01 = __floats2half2_rn(pb0.z, pb0.w);
            __half2 p10 = __floats2half2_rn(pb1.x, pb1.y);
            __half2 p11 = __floats2half2_rn(pb1.z, pb1.w);
            uint2 r0 = make_uint2(*(uint32_t*)&p00, *(uint32_t*)&p01);
            uint2 r1 = make_uint2(*(uint32_t*)&p10, *(uint32_t*)&p11);
            *(uint2*)(Bsm + (2 * bk2    ) * BSTR + bc4 * 2) = r0;
            *(uint2*)(Bsm + (2 * bk2 + 1) * BSTR + bc4 * 2) = r1;
        }
        __syncthreads();

        // ---- issue next chunk's global loads (overlap with MMAs below) ----
        if (k0 + BK < K_) {
#pragma unroll
            for (int h = 0; h < 2; h++)
                pa[h] = aok[h] ? *(const float4*)(aptr[h] + k0 + BK)
                               : make_float4(0.f, 0.f, 0.f, 0.f);
            const float* bp = bptr + (size_t)(k0 + BK) * N_;
            pb0 = *(const float4*)bp;
            pb1 = *(const float4*)(bp + N_);
        }

        // ---- fragments via ldmatrix + 16 MMAs ----
        uint32_t ah[4][4], bh[4][2];
#pragma unroll
        for (int mt = 0; mt < 4; mt++)
            ldsm_x4(ah[mt], a_addr[mt]);
#pragma unroll
        for (int p = 0; p < 2; p++) {
            uint32_t t[4];
            ldsm_x4_t(t, b_addr[p]);
            bh[2 * p    ][0] = t[0]; bh[2 * p    ][1] = t[1];
            bh[2 * p + 1][0] = t[2]; bh[2 * p + 1][1] = t[3];
        }
#pragma unroll
        for (int mt = 0; mt < 4; mt++)
#pragma unroll
            for (int nt = 0; nt < 4; nt++)
                mma_fp16(acc[mt][nt], ah[mt], bh[nt]);
        __syncthreads();
    }

    // ---- epilogue: fp16 stores ----
#pragma unroll
    for (int mt = 0; mt < 4; mt++) {
        int r0 = by * BM + wr * 64 + mt * 16 + g;
        int r1 = r0 + 8;
#pragma unroll
        for (int nt = 0; nt < 4; nt++) {
            int col = bx * BN + wc * 32 + nt * 8 + 2 * tc;
            if (r0 < NN)
                *(__half2*)(Y + (size_t)r0 * N_ + col) = __floats2half2_rn(acc[mt][nt][0], acc[mt][nt][1]);
            if (r1 < NN)
                *(__half2*)(Y + (size_t)r1 * N_ + col) = __floats2half2_rn(acc[mt][nt][2], acc[mt][nt][3]);
        }
    }
}

// ---------------- aggregation: fp16 gathers; optional fused LN stats ----------------
// blockDim = (F/4, NPB). One node per threadIdx.y. No output atomics.
template <int F, int NPB, bool SECOND, bool FUSE_STATS>
__global__ void k_agg(const float* __restrict__ bias) {
    constexpr int F4 = F / 4;
    const uint2* __restrict__ hpre = SECOND ? (const uint2*)g_h2pre : (const uint2*)g_h1pre;
    float4* __restrict__ hout      = SECOND ? (float4*)g_h2 : (float4*)g_h1;

    int n = blockIdx.x * NPB + threadIdx.y;   // NN divisible by NPB: always in range
    int f = threadIdx.x;

    float di = g_dinv[n];
    float4 self = h4_to_f4(hpre[(size_t)n * F4 + f]);
    float w_self = di * di;
    float4 acc;
    acc.x = w_self * self.x; acc.y = w_self * self.y;
    acc.z = w_self * self.z; acc.w = w_self * self.w;

    int e = g_rowptr[n];
    int end = g_rowptr[n + 1];
    for (; e + 4 <= end; e += 4) {
        int s0 = g_colsrc[e + 0], s1 = g_colsrc[e + 1];
        int s2 = g_colsrc[e + 2], s3 = g_colsrc[e + 3];
        float w0 = g_colw[e + 0], w1 = g_colw[e + 1];
        float w2 = g_colw[e + 2], w3 = g_colw[e + 3];
        float4 v0 = h4_to_f4(hpre[(size_t)s0 * F4 + f]);
        float4 v1 = h4_to_f4(hpre[(size_t)s1 * F4 + f]);
        float4 v2 = h4_to_f4(hpre[(size_t)s2 * F4 + f]);
        float4 v3 = h4_to_f4(hpre[(size_t)s3 * F4 + f]);
        acc.x = fmaf(w0, v0.x, acc.x); acc.y = fmaf(w0, v0.y, acc.y);
        acc.z = fmaf(w0, v0.z, acc.z); acc.w = fmaf(w0, v0.w, acc.w);
        acc.x = fmaf(w1, v1.x, acc.x); acc.y = fmaf(w1, v1.y, acc.y);
        acc.z = fmaf(w1, v1.z, acc.z); acc.w = fmaf(w1, v1.w, acc.w);
        acc.x = fmaf(w2, v2.x, acc.x); acc.y = fmaf(w2, v2.y, acc.y);
        acc.z = fmaf(w2, v2.z, acc.z); acc.w = fmaf(w2, v2.w, acc.w);
        acc.x = fmaf(w3, v3.x, acc.x); acc.y = fmaf(w3, v3.y, acc.y);
        acc.z = fmaf(w3, v3.z, acc.z); acc.w = fmaf(w3, v3.w, acc.w);
    }
    for (; e < end; ++e) {
        float w = g_colw[e];
        float4 v = h4_to_f4(hpre[(size_t)g_colsrc[e] * F4 + f]);
        acc.x = fmaf(w, v.x, acc.x); acc.y = fmaf(w, v.y, acc.y);
        acc.z = fmaf(w, v.z, acc.z); acc.w = fmaf(w, v.w, acc.w);
    }

    float4 b = ((const float4*)bias)[f];
    float4 o;
    o.x = fmaxf(acc.x + b.x, 0.f);
    o.y = fmaxf(acc.y + b.y, 0.f);
    o.z = fmaxf(acc.z + b.z, 0.f);
    o.w = fmaxf(acc.w + b.w, 0.f);
    hout[(size_t)n * F4 + f] = o;

    if (FUSE_STATS) {
        // block-reduce sum & sumsq of outputs -> scalar atomics (LN1 stats)
        constexpr int NT2 = F4 * NPB;
        __shared__ float rs[NT2], rq[NT2];
        int t = threadIdx.y * F4 + threadIdx.x;
        rs[t] = o.x + o.y + o.z + o.w;
        rq[t] = o.x * o.x + o.y * o.y + o.z * o.z + o.w * o.w;
        __syncthreads();
        for (int off = NT2 / 2; off > 0; off >>= 1) {
            if (t < off) { rs[t] += rs[t + off]; rq[t] += rq[t + off]; }
            __syncthreads();
        }
        if (t == 0) { atomicAdd(&g_ssum, rs[0]); atomicAdd(&g_sss, rq[0]); }
    }
}

// ---------------- reduce h2: column sums + global sumsq (512 blocks: atomics OK) ----
__global__ void k_reduce_h2() {
    int tid = threadIdx.x;
    float col = 0.f, ss = 0.f;
    int stride = gridDim.x * 256;     // multiple of 128 -> fixed channel per thread
    for (int i = blockIdx.x * 256 + tid; i < NN * FOUT; i += stride) {
        float v = g_h2[i];
        col += v;
        ss += v * v;
    }
    __shared__ float shc[256], shs[256];
    shc[tid] = col; shs[tid] = ss;
    __syncthreads();
    if (tid < 128) shc[tid] += shc[tid + 128];  // same channel pairing
    for (int o = 128; o > 0; o >>= 1) {
        if (tid < o) shs[tid] += shs[tid + o];
        __syncthreads();
    }
    if (tid < 128) atomicAdd(&g_colsum[tid], shc[tid]);
    if (tid == 0)  atomicAdd(&g_ss2, shs[0]);
}

// ---------------- final LN2 + global mean pool -> out[1,128] ----------------
__global__ void k_final(const float* __restrict__ w, const float* __restrict__ b,
                        float* __restrict__ out) {
    __shared__ float sh[128];
    int tid = threadIdx.x;
    float cs = g_colsum[tid];
    sh[tid] = cs;
    __syncthreads();
    for (int o = 64; o > 0; o >>= 1) {
        if (tid < o) sh[tid] += sh[tid + o];
        __syncthreads();
    }
    float invM = 1.f / (float)((size_t)NN * FOUT);
    float mean = sh[0] * invM;
    float var  = g_ss2 * invM - mean * mean;
    float rs   = rsqrtf(var + EPSF);
    out[tid] = (cs * (1.f / (float)NN) - mean) * rs * w[tid] + b[tid];
}

// ---------------- launch ----------------
extern "C" void kernel_launch(void* const* d_in, const int* in_sizes, int n_in,
                              void* d_out, int out_size) {
    const float* x    = (const float*)d_in[0];
    const int*   ei   = (const int*)d_in[1];
    const float* W1   = (const float*)d_in[2];
    const float* b1   = (const float*)d_in[3];
    const float* W2   = (const float*)d_in[4];
    const float* b2   = (const float*)d_in[5];
    const float* ln0w = (const float*)d_in[6];
    const float* ln0b = (const float*)d_in[7];
    const float* ln1w = (const float*)d_in[8];
    const float* ln1b = (const float*)d_in[9];
    const float* ln2w = (const float*)d_in[10];
    const float* ln2b = (const float*)d_in[11];
    const int* src = ei;
    const int* dst = ei + EE;
    float* out = (float*)d_out;

    dim3 nb256((NN + 255) / 256, 1, 1);
    dim3 eb256((EE + 255) / 256, 1, 1);

    // launches 1-3: LN0 stats/finalize + init (GEMM1 must be 4th -> profiled)
    k_stats<<<NBLK_STATS, 256>>>(x, (NN * FIN) / 4);
    k_finalize_ln<<<1, 256>>>(1.f / (float)((size_t)NN * FIN), ln0w, ln0b, FIN);
    k_init<<<nb256, 256>>>();

    // 4: layer-1 GEMM (profiled launch) — round-13 measured-optimal config
    k_gemm_fp16<FIN, FHID, false><<<dim3(FHID / 128, (NN + 127) / 128), 256>>>(x, W1);

    // CSR build
    k_deg<<<eb256, 256>>>(dst);
    k_scan1<<<NSCAN, SCAN_B>>>();
    k_scan2<<<1, 32>>>(NSCAN);
    k_scan3<<<nb256, 256>>>();
    k_scatter<<<eb256, 256>>>(src, dst);

    // layer 1 aggregate + bias + relu (+ fused LN1 stats)
    k_agg<FHID, 2, false, true><<<NN / 2, dim3(64, 2)>>>(b1);
    k_finalize_ln_s<<<1, 256>>>(1.f / (float)((size_t)NN * FHID), ln1w, ln1b, FHID);

    // layer 2 GEMM + aggregate
    k_gemm_fp16<FHID, FOUT, true><<<dim3(FOUT / 128, (NN + 127) / 128), 256>>>(nullptr, W2);
    k_agg<FOUT, 4, true, false><<<NN / 4, dim3(32, 4)>>>(b2);

    // ln2 + mean pool (512-block partial reduce keeps per-address atomic rate low)
    k_reduce_h2<<<512, 256>>>();
    k_final<<<1, FOUT>>>(ln2w, ln2b, out);
}